// round 1
// baseline (speedup 1.0000x reference)
#include <cuda_runtime.h>
#include <cuda_bf16.h>
#include <mma.h>
#include <cstdint>

using namespace nvcuda;

// Problem constants
constexpr int Bc  = 4;
constexpr int Nn  = 2048;
constexpr int Kc  = 48;
constexpr int Hc  = 128;
constexpr int CEc = 128;
constexpr int HCc = 256;   // H + CE
constexpr int FFc = 512;
constexpr float INV_SCALE = 1.0f / 30.0f;

// ---------------------------------------------------------------------------
// Device-global scratch (no cudaMalloc allowed)
// ---------------------------------------------------------------------------
__device__ __nv_bfloat16 g_W1bf[HCc * Hc];
__device__ __nv_bfloat16 g_W2bf[Hc * Hc];
__device__ __nv_bfloat16 g_W3bf[Hc * Hc];
__device__ __nv_bfloat16 g_WinHi[Hc * FFc];
__device__ __nv_bfloat16 g_WinLo[Hc * FFc];
__device__ __nv_bfloat16 g_WoutHi[FFc * Hc];
__device__ __nv_bfloat16 g_WoutLo[FFc * Hc];
__device__ float         g_h[Bc * Nn * Hc];   // h_V + dh (pre-FF)

// ---------------------------------------------------------------------------
// Helpers
// ---------------------------------------------------------------------------
__device__ __forceinline__ float gelu_tanh_f(float x) {
    float x3 = x * x * x;
    return 0.5f * x * (1.0f + tanhf(0.7978845608028654f * (x + 0.044715f * x3)));
}
__device__ __forceinline__ float gelu_erf_f(float x) {
    return x * normcdff(x);   // exact gelu: x * Phi(x)
}

using FragA = wmma::fragment<wmma::matrix_a, 16, 16, 16, __nv_bfloat16, wmma::row_major>;
using FragB = wmma::fragment<wmma::matrix_b, 16, 16, 16, __nv_bfloat16, wmma::row_major>;
using FragC = wmma::fragment<wmma::accumulator, 16, 16, 16, float>;

// ---------------------------------------------------------------------------
// Weight conversion / split kernel (runs every launch; deterministic)
// ---------------------------------------------------------------------------
__global__ void prep_kernel(const float* __restrict__ W1, const float* __restrict__ W2,
                            const float* __restrict__ W3, const float* __restrict__ Win,
                            const float* __restrict__ Wout) {
    int i = blockIdx.x * blockDim.x + threadIdx.x;   // 0..65535
    if (i < HCc * Hc) g_W1bf[i] = __float2bfloat16(W1[i]);
    if (i < Hc * Hc) {
        g_W2bf[i] = __float2bfloat16(W2[i]);
        g_W3bf[i] = __float2bfloat16(W3[i]);
    }
    if (i < Hc * FFc) {
        float v = Win[i];
        __nv_bfloat16 hi = __float2bfloat16(v);
        g_WinHi[i] = hi;
        g_WinLo[i] = __float2bfloat16(v - __bfloat162float(hi));
        v = Wout[i];
        hi = __float2bfloat16(v);
        g_WoutHi[i] = hi;
        g_WoutLo[i] = __float2bfloat16(v - __bfloat162float(hi));
    }
}

// ---------------------------------------------------------------------------
// Edge-MLP kernel: persistent, 2 nodes (96 edge rows) per tile iteration.
// smem layout (bytes):
// ---------------------------------------------------------------------------
constexpr int OFF_W1  = 0;                         // 256*136*2 = 69632
constexpr int OFF_W2  = OFF_W1 + 69632;            // 128*136*2 = 34816
constexpr int OFF_W3  = OFF_W2 + 34816;            // 34816
constexpr int OFF_A   = OFF_W3 + 34816;            // 96*264*2  = 50688 (also reused as M2)
constexpr int OFF_M1  = OFF_A + 50688;             // 96*136*2  = 26112
constexpr int OFF_SCR = OFF_M1 + 26112;            // 8*16*24*4 = 12288
constexpr int OFF_B1  = OFF_SCR + 12288;           // 512
constexpr int OFF_B2  = OFF_B1 + 512;              // 512
constexpr int OFF_B3  = OFF_B2 + 512;              // 512
constexpr int OFF_IDX = OFF_B3 + 512;              // 96*4 = 384
constexpr int OFF_MSK = OFF_IDX + 384;             // 384
constexpr int OFF_DH  = OFF_MSK + 384;             // 256*4 = 1024
constexpr int EDGE_SMEM = OFF_DH + 1024;           // 231680 bytes

// Generic layer: D[96x128] = act(A[96 x 16*ksteps] @ W + bias), bf16 out.
__device__ __forceinline__ void mlp_layer(const __nv_bfloat16* __restrict__ A, int lda,
                                          const __nv_bfloat16* __restrict__ W,
                                          const float* __restrict__ bias,
                                          __nv_bfloat16* __restrict__ D,
                                          float* scr, int ksteps, int warp, int lane) {
    const int ct = warp;           // 8 warps <-> 8 column tiles
    for (int rt = 0; rt < 6; rt += 2) {
        FragC acc0, acc1;
        wmma::fill_fragment(acc0, 0.0f);
        wmma::fill_fragment(acc1, 0.0f);
        for (int k = 0; k < ksteps; ++k) {
            FragB fb;
            FragA fa0, fa1;
            wmma::load_matrix_sync(fb, W + (k * 16) * 136 + ct * 16, 136);
            wmma::load_matrix_sync(fa0, A + (rt * 16) * lda + k * 16, lda);
            wmma::load_matrix_sync(fa1, A + ((rt + 1) * 16) * lda + k * 16, lda);
            wmma::mma_sync(acc0, fa0, fb, acc0);
            wmma::mma_sync(acc1, fa1, fb, acc1);
        }
        auto epi = [&](const FragC& acc, int rbase) {
            wmma::store_matrix_sync(scr, acc, 24, wmma::mem_row_major);
            __syncwarp();
#pragma unroll
            for (int i = 0; i < 8; ++i) {
                int e = lane + 32 * i;
                int r = e >> 4, c = e & 15;
                float v = scr[r * 24 + c] + bias[ct * 16 + c];
                v = gelu_tanh_f(v);
                D[(rbase + r) * 136 + ct * 16 + c] = __float2bfloat16(v);
            }
            __syncwarp();
        };
        epi(acc0, rt * 16);
        epi(acc1, (rt + 1) * 16);
    }
}

__global__ __launch_bounds__(256, 1)
void edge_mlp_kernel(const float* __restrict__ hV, const float* __restrict__ hE,
                     const int* __restrict__ eidx, const float* __restrict__ mAtt,
                     const float* __restrict__ b1, const float* __restrict__ b2,
                     const float* __restrict__ b3) {
    extern __shared__ __align__(16) char sm[];
    __nv_bfloat16* W1s  = reinterpret_cast<__nv_bfloat16*>(sm + OFF_W1);
    __nv_bfloat16* W2s  = reinterpret_cast<__nv_bfloat16*>(sm + OFF_W2);
    __nv_bfloat16* W3s  = reinterpret_cast<__nv_bfloat16*>(sm + OFF_W3);
    __nv_bfloat16* Abuf = reinterpret_cast<__nv_bfloat16*>(sm + OFF_A);   // stride 264 as A, 136 as M2
    __nv_bfloat16* M1   = reinterpret_cast<__nv_bfloat16*>(sm + OFF_M1);
    float* scrb   = reinterpret_cast<float*>(sm + OFF_SCR);
    float* b1s    = reinterpret_cast<float*>(sm + OFF_B1);
    float* b2s    = reinterpret_cast<float*>(sm + OFF_B2);
    float* b3s    = reinterpret_cast<float*>(sm + OFF_B3);
    int*   idx_s  = reinterpret_cast<int*>(sm + OFF_IDX);
    float* mask_s = reinterpret_cast<float*>(sm + OFF_MSK);
    float* dh_s   = reinterpret_cast<float*>(sm + OFF_DH);

    const int tid = threadIdx.x;
    const int warp = tid >> 5;
    const int lane = tid & 31;
    float* scr = scrb + warp * (16 * 24);

    // Load weights once per block (L2 -> smem, padded stride 136)
    for (int i = tid; i < HCc * Hc; i += 256)
        W1s[(i >> 7) * 136 + (i & 127)] = g_W1bf[i];
    for (int i = tid; i < Hc * Hc; i += 256) {
        int r = i >> 7, c = i & 127;
        W2s[r * 136 + c] = g_W2bf[i];
        W3s[r * 136 + c] = g_W3bf[i];
    }
    if (tid < Hc) { b1s[tid] = b1[tid]; b2s[tid] = b2[tid]; b3s[tid] = b3[tid]; }

    const int n_tiles = (Bc * Nn) / 2;   // 4096
    for (int t = blockIdx.x; t < n_tiles; t += gridDim.x) {
        __syncthreads();   // protect smem reuse across iterations
        const int node0 = t * 2;          // global node index of first node
        const int b = node0 >> 11;        // node0 / 2048

        if (tid < 96) {
            int rr = tid;
            int nl = (rr >= Kc) ? 1 : 0;
            int kk = rr - nl * Kc;
            int gn = node0 + nl;
            idx_s[rr]  = eidx[gn * Kc + kk];
            mask_s[rr] = mAtt[gn * Kc + kk];
        }
        dh_s[tid] = 0.0f;   // 256 entries, 256 threads
        __syncthreads();

        // Gather + concat + convert to bf16: A[96 x 256], stride 264
        for (int e = tid; e < 96 * 64; e += 256) {
            int row = e >> 6;
            int q = e & 63;
            float4 v;
            if (q < 32) {
                int nb = idx_s[row];
                v = reinterpret_cast<const float4*>(hV + (size_t)(b * Nn + nb) * Hc)[q];
            } else {
                int nl = (row >= Kc) ? 1 : 0;
                int kk = row - nl * Kc;
                int gn = node0 + nl;
                v = reinterpret_cast<const float4*>(hE + (size_t)(gn * Kc + kk) * CEc)[q - 32];
            }
            __nv_bfloat162* dst = reinterpret_cast<__nv_bfloat162*>(Abuf + row * 264 + q * 4);
            dst[0] = __floats2bfloat162_rn(v.x, v.y);
            dst[1] = __floats2bfloat162_rn(v.z, v.w);
        }
        __syncthreads();

        // Layer 1: [96x256] @ [256x128] -> M1
        mlp_layer(Abuf, 264, W1s, b1s, M1, scr, 16, warp, lane);
        __syncthreads();

        // Layer 2: M1 @ W2 -> M2 (reuses Abuf region, stride 136)
        __nv_bfloat16* M2 = Abuf;
        mlp_layer(M1, 136, W2s, b2s, M2, scr, 8, warp, lane);
        __syncthreads();

        // Layer 3: M2 @ W3 + b3, mask, column-reduce into dh_s
        {
            const int ct = warp;
            for (int rt = 0; rt < 6; rt += 2) {
                FragC acc0, acc1;
                wmma::fill_fragment(acc0, 0.0f);
                wmma::fill_fragment(acc1, 0.0f);
                for (int k = 0; k < 8; ++k) {
                    FragB fb;
                    FragA fa0, fa1;
                    wmma::load_matrix_sync(fb, W3s + (k * 16) * 136 + ct * 16, 136);
                    wmma::load_matrix_sync(fa0, M2 + (rt * 16) * 136 + k * 16, 136);
                    wmma::load_matrix_sync(fa1, M2 + ((rt + 1) * 16) * 136 + k * 16, 136);
                    wmma::mma_sync(acc0, fa0, fb, acc0);
                    wmma::mma_sync(acc1, fa1, fb, acc1);
                }
                auto epi3 = [&](const FragC& acc, int rbase) {
                    wmma::store_matrix_sync(scr, acc, 24, wmma::mem_row_major);
                    __syncwarp();
                    int node = (rbase >= Kc) ? 1 : 0;
                    float partial = 0.0f;
#pragma unroll
                    for (int i = 0; i < 8; ++i) {
                        int e = lane + 32 * i;
                        int r = e >> 4, c = e & 15;
                        float v = scr[r * 24 + c] + b3s[ct * 16 + c];
                        v *= mask_s[rbase + r];
                        partial += v;
                    }
                    partial += __shfl_xor_sync(0xffffffffu, partial, 16);
                    if (lane < 16)
                        atomicAdd(&dh_s[node * Hc + ct * 16 + (lane & 15)], partial);
                    __syncwarp();
                };
                epi3(acc0, rt * 16);
                epi3(acc1, (rt + 1) * 16);
            }
        }
        __syncthreads();

        // h = h_V + dh/SCALE  -> staging buffer
        {
            int node = tid >> 7, col = tid & 127;
            int gn = node0 + node;
            int gi = gn * Hc + col;
            g_h[gi] = hV[gi] + dh_s[tid] * INV_SCALE;
        }
    }
}

// ---------------------------------------------------------------------------
// FF kernel: 64 nodes per block, split-bf16 (hi+lo) for accuracy.
// ---------------------------------------------------------------------------
constexpr int FOFF_AHI = 0;                    // 64*136*2 = 17408
constexpr int FOFF_ALO = FOFF_AHI + 17408;
constexpr int FOFF_WIH = FOFF_ALO + 17408;     // 128*136*2 = 34816
constexpr int FOFF_WIL = FOFF_WIH + 34816;
constexpr int FOFF_HHI = FOFF_WIL + 34816;     // 17408
constexpr int FOFF_HLO = FOFF_HHI + 17408;
constexpr int FOFF_WOH = FOFF_HLO + 17408;     // 34816
constexpr int FOFF_WOL = FOFF_WOH + 34816;
constexpr int FOFF_SCR = FOFF_WOL + 34816;     // 12288
constexpr int FOFF_BIN = FOFF_SCR + 12288;     // 2048
constexpr int FOFF_BOUT= FOFF_BIN + 2048;      // 512
constexpr int FOFF_MV  = FOFF_BOUT + 512;      // 256
constexpr int FF_SMEM  = FOFF_MV + 256;        // 224000 bytes

__global__ __launch_bounds__(256, 1)
void ff_kernel(const float* __restrict__ maskV, const float* __restrict__ b_in,
               const float* __restrict__ b_out, float* __restrict__ out) {
    extern __shared__ __align__(16) char sm[];
    __nv_bfloat16* Ahi = reinterpret_cast<__nv_bfloat16*>(sm + FOFF_AHI);
    __nv_bfloat16* Alo = reinterpret_cast<__nv_bfloat16*>(sm + FOFF_ALO);
    __nv_bfloat16* WIH = reinterpret_cast<__nv_bfloat16*>(sm + FOFF_WIH);
    __nv_bfloat16* WIL = reinterpret_cast<__nv_bfloat16*>(sm + FOFF_WIL);
    __nv_bfloat16* HHI = reinterpret_cast<__nv_bfloat16*>(sm + FOFF_HHI);
    __nv_bfloat16* HLO = reinterpret_cast<__nv_bfloat16*>(sm + FOFF_HLO);
    __nv_bfloat16* WOH = reinterpret_cast<__nv_bfloat16*>(sm + FOFF_WOH);
    __nv_bfloat16* WOL = reinterpret_cast<__nv_bfloat16*>(sm + FOFF_WOL);
    float* scrb  = reinterpret_cast<float*>(sm + FOFF_SCR);
    float* bins  = reinterpret_cast<float*>(sm + FOFF_BIN);
    float* bouts = reinterpret_cast<float*>(sm + FOFF_BOUT);
    float* mvs   = reinterpret_cast<float*>(sm + FOFF_MV);

    const int tid = threadIdx.x;
    const int warp = tid >> 5;
    const int lane = tid & 31;
    const int rowbase = blockIdx.x * 64;
    float* scr = scrb + warp * (16 * 24);

    for (int i = tid; i < FFc; i += 256) bins[i] = b_in[i];
    if (tid < Hc) bouts[tid] = b_out[tid];
    if (tid < 64) mvs[tid] = maskV[rowbase + tid];

    // Load + split A = g_h rows
    for (int e = tid; e < 64 * 32; e += 256) {
        int r = e >> 5, q = e & 31;
        float4 v = reinterpret_cast<const float4*>(g_h + (size_t)(rowbase + r) * Hc)[q];
        __nv_bfloat16 hx = __float2bfloat16(v.x); float lx = v.x - __bfloat162float(hx);
        __nv_bfloat16 hy = __float2bfloat16(v.y); float ly = v.y - __bfloat162float(hy);
        __nv_bfloat16 hz = __float2bfloat16(v.z); float lz = v.z - __bfloat162float(hz);
        __nv_bfloat16 hw = __float2bfloat16(v.w); float lw = v.w - __bfloat162float(hw);
        __nv_bfloat162* dh_ = reinterpret_cast<__nv_bfloat162*>(Ahi + r * 136 + q * 4);
        dh_[0] = __halves2bfloat162(hx, hy);
        dh_[1] = __halves2bfloat162(hz, hw);
        __nv_bfloat162* dl_ = reinterpret_cast<__nv_bfloat162*>(Alo + r * 136 + q * 4);
        dl_[0] = __floats2bfloat162_rn(lx, ly);
        dl_[1] = __floats2bfloat162_rn(lz, lw);
    }

    FragC accO[4];
#pragma unroll
    for (int j = 0; j < 4; ++j) wmma::fill_fragment(accO[j], 0.0f);

    const int ct = warp;
    for (int cc = 0; cc < 4; ++cc) {      // 4 chunks of 128 over FF=512
        __syncthreads();
        // Load weight chunks
        for (int i = tid; i < Hc * 128; i += 256) {
            int r = i >> 7, c = i & 127;
            WIH[r * 136 + c] = g_WinHi[r * FFc + cc * 128 + c];
            WIL[r * 136 + c] = g_WinLo[r * FFc + cc * 128 + c];
            WOH[r * 136 + c] = g_WoutHi[(cc * 128 + r) * Hc + c];
            WOL[r * 136 + c] = g_WoutLo[(cc * 128 + r) * Hc + c];
        }
        __syncthreads();

        // GEMM1: hidden = gelu_exact(A @ Win_chunk + b_in_chunk), split hi/lo
        for (int rt = 0; rt < 4; rt += 2) {
            FragC acc0, acc1;
            wmma::fill_fragment(acc0, 0.0f);
            wmma::fill_fragment(acc1, 0.0f);
            for (int k = 0; k < 8; ++k) {
                FragB fbh, fbl;
                FragA fah0, fal0, fah1, fal1;
                wmma::load_matrix_sync(fbh, WIH + (k * 16) * 136 + ct * 16, 136);
                wmma::load_matrix_sync(fbl, WIL + (k * 16) * 136 + ct * 16, 136);
                wmma::load_matrix_sync(fah0, Ahi + (rt * 16) * 136 + k * 16, 136);
                wmma::load_matrix_sync(fal0, Alo + (rt * 16) * 136 + k * 16, 136);
                wmma::load_matrix_sync(fah1, Ahi + ((rt + 1) * 16) * 136 + k * 16, 136);
                wmma::load_matrix_sync(fal1, Alo + ((rt + 1) * 16) * 136 + k * 16, 136);
                wmma::mma_sync(acc0, fah0, fbh, acc0);
                wmma::mma_sync(acc0, fah0, fbl, acc0);
                wmma::mma_sync(acc0, fal0, fbh, acc0);
                wmma::mma_sync(acc1, fah1, fbh, acc1);
                wmma::mma_sync(acc1, fah1, fbl, acc1);
                wmma::mma_sync(acc1, fal1, fbh, acc1);
            }
            auto epiH = [&](const FragC& acc, int rbase) {
                wmma::store_matrix_sync(scr, acc, 24, wmma::mem_row_major);
                __syncwarp();
#pragma unroll
                for (int i = 0; i < 8; ++i) {
                    int e = lane + 32 * i;
                    int r = e >> 4, c = e & 15;
                    float v = scr[r * 24 + c] + bins[cc * 128 + ct * 16 + c];
                    v = gelu_erf_f(v);
                    __nv_bfloat16 hi = __float2bfloat16(v);
                    float lo = v - __bfloat162float(hi);
                    HHI[(rbase + r) * 136 + ct * 16 + c] = hi;
                    HLO[(rbase + r) * 136 + ct * 16 + c] = __float2bfloat16(lo);
                }
                __syncwarp();
            };
            epiH(acc0, rt * 16);
            epiH(acc1, (rt + 1) * 16);
        }
        __syncthreads();

        // GEMM2: out += hidden @ Wout_chunk (accumulate in registers across chunks)
#pragma unroll
        for (int rp = 0; rp < 4; rp += 2) {
            for (int k = 0; k < 8; ++k) {
                FragB fbh, fbl;
                FragA fah0, fal0, fah1, fal1;
                wmma::load_matrix_sync(fbh, WOH + (k * 16) * 136 + ct * 16, 136);
                wmma::load_matrix_sync(fbl, WOL + (k * 16) * 136 + ct * 16, 136);
                wmma::load_matrix_sync(fah0, HHI + (rp * 16) * 136 + k * 16, 136);
                wmma::load_matrix_sync(fal0, HLO + (rp * 16) * 136 + k * 16, 136);
                wmma::load_matrix_sync(fah1, HHI + ((rp + 1) * 16) * 136 + k * 16, 136);
                wmma::load_matrix_sync(fal1, HLO + ((rp + 1) * 16) * 136 + k * 16, 136);
                wmma::mma_sync(accO[rp], fah0, fbh, accO[rp]);
                wmma::mma_sync(accO[rp], fah0, fbl, accO[rp]);
                wmma::mma_sync(accO[rp], fal0, fbh, accO[rp]);
                wmma::mma_sync(accO[rp + 1], fah1, fbh, accO[rp + 1]);
                wmma::mma_sync(accO[rp + 1], fah1, fbl, accO[rp + 1]);
                wmma::mma_sync(accO[rp + 1], fal1, fbh, accO[rp + 1]);
            }
        }
    }

    // Final epilogue: out = (h + ff) * mask_V
#pragma unroll
    for (int j = 0; j < 4; ++j) {
        wmma::store_matrix_sync(scr, accO[j], 24, wmma::mem_row_major);
        __syncwarp();
        int rbase = j * 16;
#pragma unroll
        for (int i = 0; i < 8; ++i) {
            int e = lane + 32 * i;
            int r = e >> 4, c = e & 15;
            int rg = rowbase + rbase + r;
            int col = ct * 16 + c;
            float v = scr[r * 24 + c] + bouts[col];
            int gi = rg * Hc + col;
            out[gi] = (g_h[gi] + v) * mvs[rbase + r];
        }
        __syncwarp();
    }
}

// ---------------------------------------------------------------------------
// Launch
// ---------------------------------------------------------------------------
extern "C" void kernel_launch(void* const* d_in, const int* in_sizes, int n_in,
                              void* d_out, int out_size) {
    (void)in_sizes; (void)n_in; (void)out_size;
    const float* hV    = (const float*)d_in[0];
    const float* hE    = (const float*)d_in[1];
    const int*   eidx  = (const int*)d_in[2];
    const float* maskV = (const float*)d_in[3];
    const float* mAtt  = (const float*)d_in[4];
    const float* W1    = (const float*)d_in[5];
    const float* b1    = (const float*)d_in[6];
    const float* W2    = (const float*)d_in[7];
    const float* b2    = (const float*)d_in[8];
    const float* W3    = (const float*)d_in[9];
    const float* b3    = (const float*)d_in[10];
    const float* Win   = (const float*)d_in[11];
    const float* binp  = (const float*)d_in[12];
    const float* Wout  = (const float*)d_in[13];
    const float* boutp = (const float*)d_in[14];
    float* out = (float*)d_out;

    cudaFuncSetAttribute(edge_mlp_kernel, cudaFuncAttributeMaxDynamicSharedMemorySize, EDGE_SMEM);
    cudaFuncSetAttribute(ff_kernel, cudaFuncAttributeMaxDynamicSharedMemorySize, FF_SMEM);

    prep_kernel<<<128, 512>>>(W1, W2, W3, Win, Wout);
    edge_mlp_kernel<<<148, 256, EDGE_SMEM>>>(hV, hE, eidx, mAtt, b1, b2, b3);
    ff_kernel<<<(Bc * Nn) / 64, 256, FF_SMEM>>>(maskV, binp, boutp, out);
}